// round 9
// baseline (speedup 1.0000x reference)
#include <cuda_runtime.h>
#include <cstdint>
#include <math.h>

// CBOW negative-sampling loss.
//   d_in[0]: in_embed  float32 [100000, 128]
//   d_in[1]: out_embed float32 [100000, 128]
//   d_in[2]: context   int32   [B, 8]
//   d_in[3]: target    int32   [B]
//   d_in[4]: negatives int32   [B, 10]
// Output: float32 [B]
//
// Round 9 (round 8 with compile fix: <cstdint>). cp.async staging to
// decouple memory-level parallelism from registers. One element per warp,
// 4 per 128-thread CTA. Each warp issues all 19 row-copies (cp.async.cg,
// 16B per lane) back-to-back into smem: 19 rows x 512B staged with ZERO
// register cost per outstanding load. 38KB static smem -> 5 CTAs/SM ->
// ~380 rows in flight per SM, far above the ~40 needed to sustain the
// L2-throughput floor (~13us for 159MB). Each lane reads back only its
// own 16B slot, so cp.async.wait_all + __syncwarp suffices (no bar.sync).

#define CTX   8
#define NEG   10
#define D     128
#define ROWS  (CTX + 1 + NEG)      // 19
#define WPB   4                    // warps per block (1 element each)

__device__ __forceinline__ float log_sigmoid_fast(float x) {
    return fminf(x, 0.0f) - __logf(1.0f + __expf(-fabsf(x)));
}

__device__ __forceinline__ float dot4(float4 a, float4 b) {
    return a.x * b.x + a.y * b.y + a.z * b.z + a.w * b.w;
}

__device__ __forceinline__ void cp_async16(unsigned int saddr, const void* gptr) {
    asm volatile("cp.async.cg.shared.global [%0], [%1], 16;"
                 :: "r"(saddr), "l"(gptr) : "memory");
}

__global__ __launch_bounds__(32 * WPB) void cbow_neg_kernel(
    const float* __restrict__ in_embed,
    const float* __restrict__ out_embed,
    const int*   __restrict__ context,
    const int*   __restrict__ target,
    const int*   __restrict__ negatives,
    float*       __restrict__ out,
    int B)
{
    __shared__ float4 stage[WPB][ROWS][32];   // 4*19*512B = 38912B

    const int warp = threadIdx.x >> 5;
    const int lane = threadIdx.x & 31;
    const int e    = blockIdx.x * WPB + warp;
    if (e >= B) return;                       // B % 4 == 0

    // ---- 19 row indices (warp-uniform loads, L1 broadcast) ----
    int idx[ROWS];
    #pragma unroll
    for (int c = 0; c < CTX; c++) idx[c] = __ldg(&context[e * CTX + c]);
    idx[CTX] = __ldg(&target[e]);
    #pragma unroll
    for (int k = 0; k < NEG; k++) idx[CTX + 1 + k] = __ldg(&negatives[e * NEG + k]);

    // ---- stage all 19 rows via cp.async (16B per lane per row) ----
    #pragma unroll
    for (int r = 0; r < ROWS; r++) {
        const float* table = (r < CTX) ? in_embed : out_embed;
        const float* src   = table + (size_t)idx[r] * D + lane * 4;
        unsigned int dst =
            (unsigned int)__cvta_generic_to_shared(&stage[warp][r][lane]);
        cp_async16(dst, src);
    }
    asm volatile("cp.async.wait_all;" ::: "memory");
    __syncwarp();

    // ---- v = mean of 8 context rows (this lane's float4 slot) ----
    float4 v = stage[warp][0][lane];
    #pragma unroll
    for (int c = 1; c < CTX; c++) {
        const float4 a = stage[warp][c][lane];
        v.x += a.x; v.y += a.y; v.z += a.z; v.w += a.w;
    }
    const float inv = 1.0f / (float)CTX;
    v.x *= inv; v.y *= inv; v.z *= inv; v.w *= inv;

    // ---- 11 per-lane partial dots (target + 10 negatives) ----
    float s[NEG + 1];
    #pragma unroll
    for (int i = 0; i < NEG + 1; i++)
        s[i] = dot4(v, stage[warp][CTX + i][lane]);

    // ---- butterfly-reduce each score across the warp ----
    #pragma unroll
    for (int i = 0; i < NEG + 1; i++) {
        float x = s[i];
        x += __shfl_xor_sync(0xffffffffu, x, 16);
        x += __shfl_xor_sync(0xffffffffu, x, 8);
        x += __shfl_xor_sync(0xffffffffu, x, 4);
        x += __shfl_xor_sync(0xffffffffu, x, 2);
        x += __shfl_xor_sync(0xffffffffu, x, 1);
        s[i] = x;
    }

    // ---- epilogue ----
    if (lane == 0) {
        float acc = log_sigmoid_fast(s[0]);
        #pragma unroll
        for (int k = 0; k < NEG; k++)
            acc += log_sigmoid_fast(-s[1 + k]);
        out[e] = -acc;
    }
}

extern "C" void kernel_launch(void* const* d_in, const int* in_sizes, int n_in,
                              void* d_out, int out_size)
{
    const float* in_embed  = (const float*)d_in[0];
    const float* out_embed = (const float*)d_in[1];
    const int*   context   = (const int*)d_in[2];
    const int*   target    = (const int*)d_in[3];
    const int*   negatives = (const int*)d_in[4];
    float*       out       = (float*)d_out;

    const int B = out_size;                       // 16384
    const int blocks = (B + WPB - 1) / WPB;       // 4096
    cbow_neg_kernel<<<blocks, 32 * WPB>>>(in_embed, out_embed, context, target,
                                          negatives, out, B);
}